// round 1
// baseline (speedup 1.0000x reference)
#include <cuda_runtime.h>
#include <cuda_bf16.h>
#include <cstddef>

// StreamingPCEN: x[16,4,2048,257] f32.
//   M_0 = x_0 ; M_t = (1-s) M_{t-1} + s x_t   (recurrence over T=2048, per (bm,f))
//   out = (x * (M+eps)^(-alpha) + delta)^r - delta^r
//
// Two-level exact scan: C=16 chunks of L=128 frames.
//   Phase A: per-(row=bm*C+chunk, f) thread computes zero-carry chunk EMA -> g_b
//   Phase C: fold carries (<=15 FMAs from L2-hot g_b), re-run recurrence, emit out.

#define PCEN_EPS 1e-6f

constexpr int BM      = 64;          // 16 batch * 4 mics
constexpr int T       = 2048;
constexpr int F       = 257;
constexpr int CHUNKS  = 16;
constexpr int L       = 128;         // CHUNKS * L == T
constexpr int NROW    = BM * CHUNKS; // 1024
constexpr int NTHR    = NROW * F;    // 263168
constexpr int TPB     = 256;

__device__ float g_b[NROW * F];      // 1.03 MB scratch (chunk carries)

__global__ void __launch_bounds__(TPB)
pcen_phaseA(const float* __restrict__ x, const float* __restrict__ s_p)
{
    int idx = blockIdx.x * TPB + threadIdx.x;
    if (idx >= NTHR) return;
    int row   = idx / F;             // bm*CHUNKS + chunk
    int f     = idx - row * F;
    int chunk = row & (CHUNKS - 1);

    const float s = __ldg(s_p);
    const float* px = x + (size_t)row * (L * F) + f;

    float v0 = __ldg(px);
    // chunk 0: M_0 = x_0 (special first frame); others: carry=0 -> m = s*v0
    float m = (chunk == 0) ? v0 : s * v0;

#pragma unroll 8
    for (int t = 1; t < L; ++t) {
        float v = __ldg(px + t * F);
        m = fmaf(s, v - m, m);       // (1-s)*m + s*v
    }
    g_b[idx] = m;
}

__global__ void __launch_bounds__(TPB)
pcen_phaseC(const float* __restrict__ x,
            const float* __restrict__ s_p,
            const float* __restrict__ a_p,
            const float* __restrict__ d_p,
            const float* __restrict__ r_p,
            float* __restrict__ out)
{
    int idx = blockIdx.x * TPB + threadIdx.x;
    if (idx >= NTHR) return;
    int row   = idx / F;
    int f     = idx - row * F;
    int chunk = row & (CHUNKS - 1);

    const float s     = __ldg(s_p);
    const float alpha = __ldg(a_p);
    const float delta = __ldg(d_p);
    const float r     = __ldg(r_p);

    const float A   = __powf(1.0f - s, (float)L);   // chunk decay
    const float dpr = __powf(delta, r);
    const float na  = -alpha;
    const bool rhalf = (r == 0.5f);

    // Fold carries: carry_in(chunk) = M at end of chunk-1.
    // c_i = A*c_{i-1} + b_i, i ascending from 0.
    const float* pb = &g_b[(row - chunk) * F + f];
    float c = 0.0f;
    for (int i = 0; i < chunk; ++i)
        c = fmaf(A, c, __ldg(pb + i * F));

    const float* px = x + (size_t)row * (L * F) + f;
    float*       po = out + (size_t)row * (L * F) + f;

    // t = 0 (peeled: chunk 0 uses M_0 = x_0)
    float v = __ldg(px);
    float m = (chunk == 0) ? v : fmaf(s, v - c, c);
    {
        float y = m + PCEN_EPS;
        float p = __powf(y, na);
        float z = fmaf(v, p, delta);
        float o = rhalf ? sqrtf(z) : __powf(z, r);
        po[0] = o - dpr;
    }

#pragma unroll 4
    for (int t = 1; t < L; ++t) {
        v = __ldg(px + t * F);
        m = fmaf(s, v - m, m);
        float y = m + PCEN_EPS;
        float p = __powf(y, na);          // (M+eps)^(-alpha)
        float z = fmaf(v, p, delta);
        float o = rhalf ? sqrtf(z) : __powf(z, r);
        po[t * F] = o - dpr;
    }
}

extern "C" void kernel_launch(void* const* d_in, const int* in_sizes, int n_in,
                              void* d_out, int out_size)
{
    const float* x     = (const float*)d_in[0];
    const float* s     = (const float*)d_in[1];
    const float* alpha = (const float*)d_in[2];
    const float* delta = (const float*)d_in[3];
    const float* r     = (const float*)d_in[4];
    float* out = (float*)d_out;

    int blocks = (NTHR + TPB - 1) / TPB;
    pcen_phaseA<<<blocks, TPB>>>(x, s);
    pcen_phaseC<<<blocks, TPB>>>(x, s, alpha, delta, r, out);
}

// round 2
// speedup vs baseline: 1.2999x; 1.2999x over previous
#include <cuda_runtime.h>
#include <cuda_bf16.h>
#include <cstddef>

// StreamingPCEN: x[16,4,2048,257] f32.
//   M_0 = x_0 ; M_t = (1-s) M_{t-1} + s x_t   (recurrence over T=2048, per (bm,f))
//   out = (x * (M+eps)^(-alpha) + delta)^r - delta^r
//
// Two-level exact scan: 16 chunks of L=128 frames.
//   Phase A: per-(row=bm*16+chunk, fpair) thread computes zero-carry chunk EMA -> g_b
//   Phase C: fold carries (<=15 FMAs, L2-hot g_b), re-run recurrence, emit out.
//
// R2 changes: ILP-2 (two f-columns per thread: f and f+129, second predicated)
// + explicit 8-frame load batching => MLP ~16/thread to hide DRAM latency.

#define PCEN_EPS 1e-6f

constexpr int BM      = 64;           // 16 batch * 4 mics
constexpr int T       = 2048;
constexpr int F       = 257;
constexpr int CHUNKS  = 16;
constexpr int L       = 128;          // CHUNKS * L == T
constexpr int NROW    = BM * CHUNKS;  // 1024
constexpr int FH      = 129;          // column-pair stride (f, f+FH)
constexpr int NTHR    = NROW * FH;    // 132096 threads
constexpr int TPB     = 256;
constexpr int VT      = 8;            // frames per load batch

__device__ float g_b[NROW * F];       // 1.03 MB scratch (chunk carries)

__global__ void __launch_bounds__(TPB)
pcen_phaseA(const float* __restrict__ x, const float* __restrict__ s_p)
{
    int idx = blockIdx.x * TPB + threadIdx.x;
    if (idx >= NTHR) return;
    int row   = idx / FH;             // bm*CHUNKS + chunk
    int f     = idx - row * FH;
    bool two  = (f + FH) < F;         // false only for f==128
    int chunk = row & (CHUNKS - 1);

    const float s = __ldg(s_p);
    const float* px = x + (size_t)row * (L * F) + f;

    float m0 = 0.0f, m1 = 0.0f;

#pragma unroll 1
    for (int tb = 0; tb < L; tb += VT) {
        float a[VT], b[VT];
#pragma unroll
        for (int j = 0; j < VT; ++j) {
            a[j] = __ldg(px + (tb + j) * F);
            b[j] = two ? __ldg(px + (tb + j) * F + FH) : 0.0f;
        }
#pragma unroll
        for (int j = 0; j < VT; ++j) {
            if (j == 0 && tb == 0) {
                // first frame: chunk 0 -> M_0 = x_0 ; else zero-carry -> s*x
                m0 = (chunk == 0) ? a[0] : s * a[0];
                m1 = (chunk == 0) ? b[0] : s * b[0];
            } else {
                m0 = fmaf(s, a[j] - m0, m0);   // (1-s)*m + s*v
                m1 = fmaf(s, b[j] - m1, m1);
            }
        }
    }
    g_b[(size_t)row * F + f] = m0;
    if (two) g_b[(size_t)row * F + f + FH] = m1;
}

__global__ void __launch_bounds__(TPB)
pcen_phaseC(const float* __restrict__ x,
            const float* __restrict__ s_p,
            const float* __restrict__ a_p,
            const float* __restrict__ d_p,
            const float* __restrict__ r_p,
            float* __restrict__ out)
{
    int idx = blockIdx.x * TPB + threadIdx.x;
    if (idx >= NTHR) return;
    int row   = idx / FH;
    int f     = idx - row * FH;
    bool two  = (f + FH) < F;
    int chunk = row & (CHUNKS - 1);

    const float s     = __ldg(s_p);
    const float alpha = __ldg(a_p);
    const float delta = __ldg(d_p);
    const float r     = __ldg(r_p);

    const float A    = __powf(1.0f - s, (float)L);   // chunk decay
    const float dpr  = __powf(delta, r);
    const float na   = -alpha;
    const bool rhalf = (r == 0.5f);

    // Fold carries: carry_in(chunk) = M at end of chunk-1.
    const float* pb = &g_b[(size_t)(row - chunk) * F + f];
    float c0 = 0.0f, c1 = 0.0f;
    for (int i = 0; i < chunk; ++i) {
        c0 = fmaf(A, c0, __ldg(pb + i * F));
        c1 = two ? fmaf(A, c1, __ldg(pb + i * F + FH)) : 0.0f;
    }

    const float* px = x + (size_t)row * (L * F) + f;
    float*       po = out + (size_t)row * (L * F) + f;

    float m0 = 0.0f, m1 = 0.0f;

#pragma unroll 1
    for (int tb = 0; tb < L; tb += VT) {
        float a[VT], b[VT];
#pragma unroll
        for (int j = 0; j < VT; ++j) {
            a[j] = __ldg(px + (tb + j) * F);
            b[j] = two ? __ldg(px + (tb + j) * F + FH) : 0.0f;
        }
#pragma unroll
        for (int j = 0; j < VT; ++j) {
            if (j == 0 && tb == 0) {
                m0 = (chunk == 0) ? a[0] : fmaf(s, a[0] - c0, c0);
                m1 = (chunk == 0) ? b[0] : fmaf(s, b[0] - c1, c1);
            } else {
                m0 = fmaf(s, a[j] - m0, m0);
                m1 = fmaf(s, b[j] - m1, m1);
            }
            // pointwise: (v*(M+eps)^(-alpha) + delta)^r - delta^r
            float p0 = __powf(m0 + PCEN_EPS, na);
            float z0 = fmaf(a[j], p0, delta);
            float o0 = rhalf ? sqrtf(z0) : __powf(z0, r);
            po[(tb + j) * F] = o0 - dpr;

            if (two) {
                float p1 = __powf(m1 + PCEN_EPS, na);
                float z1 = fmaf(b[j], p1, delta);
                float o1 = rhalf ? sqrtf(z1) : __powf(z1, r);
                po[(tb + j) * F + FH] = o1 - dpr;
            }
        }
    }
}

extern "C" void kernel_launch(void* const* d_in, const int* in_sizes, int n_in,
                              void* d_out, int out_size)
{
    const float* x     = (const float*)d_in[0];
    const float* s     = (const float*)d_in[1];
    const float* alpha = (const float*)d_in[2];
    const float* delta = (const float*)d_in[3];
    const float* r     = (const float*)d_in[4];
    float* out = (float*)d_out;

    int blocks = (NTHR + TPB - 1) / TPB;   // 516
    pcen_phaseA<<<blocks, TPB>>>(x, s);
    pcen_phaseC<<<blocks, TPB>>>(x, s, alpha, delta, r, out);
}